// round 13
// baseline (speedup 1.0000x reference)
#include <cuda_runtime.h>
#include <cuda_bf16.h>
#include <cfloat>

// Problem constants (S=4096 tokens, D=1024 dim, E=64 experts)
constexpr int S   = 4096;
constexpr int D   = 1024;
constexpr int E   = 64;
constexpr int CAP = 512;          // 2 * ceil(S / (E/4))
constexpr int NCHAIN = 64;        // fused gemm+gate blocks (64 tokens each)
constexpr int ROW  = E * CAP;     // 32768 floats per token per tensor
// out layout (float32): [0] = l_aux, [1 .. 1+S*E*CAP) = combine, then dispatch

// ---------------- scratch (device globals; no allocation allowed) ----------
__device__ float g_logits1[S * E];
__device__ float g_logits2[S * E];
__device__ int   g_expert[S];
__device__ float g_gate[S];
__device__ int   g_loc[S];
__device__ float g_me_part[NCHAIN * E];
__device__ float g_laux;

// ---------------- side stream + events (R2/R8/R12-proven pattern) ----------
static cudaStream_t g_s1 = nullptr;
static cudaEvent_t  g_evFork = nullptr, g_evJoin = nullptr;
namespace {
struct StreamInit {
    StreamInit() {
        if (cudaStreamCreateWithFlags(&g_s1, cudaStreamNonBlocking) != cudaSuccess)
            g_s1 = nullptr;
        if (cudaEventCreateWithFlags(&g_evFork, cudaEventDisableTiming) != cudaSuccess)
            g_evFork = nullptr;
        if (cudaEventCreateWithFlags(&g_evJoin, cudaEventDisableTiming) != cudaSuccess)
            g_evJoin = nullptr;
    }
};
static StreamInit g_streamInit;
}

// ---------------- bulk zero fill (R12: 7.0 TB/s measured) ------------------
// 8192 blocks x 256 threads; block b zeroes float4s [b*8192, (b+1)*8192),
// which exactly covers n4 = 2*S*ROW/4. No bounds check in the hot loop.
constexpr int ZF_BLOCKS = 2 * S;                  // 8192
constexpr int ZF_CHUNK4 = 8192;                   // float4s per block (128 KB)

__global__ __launch_bounds__(256) void zero_fill_kernel(
    float4* __restrict__ p4,
    float* __restrict__ out, long long n4, long long out_elems)
{
    const float4 z = make_float4(0.f, 0.f, 0.f, 0.f);
    float4* base = p4 + (long long)blockIdx.x * ZF_CHUNK4;
#pragma unroll 4
    for (int j = threadIdx.x; j < ZF_CHUNK4; j += 256)
        base[j] = z;
    if (blockIdx.x == 0) {            // scalar tail (out_size % 4 elements)
        for (long long j = n4 * 4 + threadIdx.x; j < out_elems; j += 256)
            out[j] = 0.0f;
    }
}

// ---------------- fused chain: both GEMMs + gate, 64 blocks ----------------
// Block b handles tokens b*64..b*64+63. Tile 64 tok x 64 exp (full E), K
// chunks of 32 (16 KB smem). After both gemms, warps gate 8 tokens each.
__global__ __launch_bounds__(256) void chain_kernel(
    const float* __restrict__ A1, const float* __restrict__ A2,
    const float* __restrict__ W1, const float* __restrict__ W2)
{
    __shared__ float sA[64 * 32];
    __shared__ float sW[64 * 32];

    const int b    = blockIdx.x;
    const int tid  = threadIdx.x;
    const int lane = tid & 31;
    const int w    = tid >> 5;

    const int tok0 = b * 64;
    const int tr = tid & 15;         // token quad
    const int ec = tid >> 4;         // expert quad
    const int lrow = tid >> 3;       // loader row 0..31 (and +32)
    const int lc   = tid & 7;        // loader float4 col 0..7

    for (int p = 0; p < 2; p++) {
        const float* A = p ? A2 : A1;
        const float* W = p ? W2 : W1;
        float* lo      = p ? g_logits2 : g_logits1;

        float acc[4][4];
#pragma unroll
        for (int i = 0; i < 4; i++)
#pragma unroll
            for (int j = 0; j < 4; j++) acc[i][j] = 0.0f;

        float4 pa0, pa1, pw0, pw1;
        pa0 = *(const float4*)&A[(size_t)(tok0 + lrow) * D + lc * 4];
        pa1 = *(const float4*)&A[(size_t)(tok0 + lrow + 32) * D + lc * 4];
        pw0 = *(const float4*)&W[(size_t)lrow * D + lc * 4];
        pw1 = *(const float4*)&W[(size_t)(lrow + 32) * D + lc * 4];

        for (int kt = 0; kt < D; kt += 32) {
            {   // store with XOR swizzle: phys col = lc ^ ((row>>2)&7)
                int sc0 = (lc ^ ((lrow >> 2) & 7)) * 4;
                int sc1 = (lc ^ (((lrow + 32) >> 2) & 7)) * 4;
                *(float4*)&sA[lrow * 32 + sc0]        = pa0;
                *(float4*)&sA[(lrow + 32) * 32 + sc1] = pa1;
                *(float4*)&sW[lrow * 32 + sc0]        = pw0;
                *(float4*)&sW[(lrow + 32) * 32 + sc1] = pw1;
            }
            __syncthreads();

            if (kt + 32 < D) {
                pa0 = *(const float4*)&A[(size_t)(tok0 + lrow) * D + kt + 32 + lc * 4];
                pa1 = *(const float4*)&A[(size_t)(tok0 + lrow + 32) * D + kt + 32 + lc * 4];
                pw0 = *(const float4*)&W[(size_t)lrow * D + kt + 32 + lc * 4];
                pw1 = *(const float4*)&W[(size_t)(lrow + 32) * D + kt + 32 + lc * 4];
            }

#pragma unroll
            for (int kk = 0; kk < 8; kk++) {
                float4 av[4], wv[4];
#pragma unroll
                for (int i = 0; i < 4; i++) {
                    int tok = tr * 4 + i;
                    av[i] = *(const float4*)&sA[tok * 32 + ((kk ^ (tr & 7)) * 4)];
                    int e = ec * 4 + i;
                    wv[i] = *(const float4*)&sW[e * 32 + ((kk ^ (ec & 7)) * 4)];
                }
#pragma unroll
                for (int i = 0; i < 4; i++)
#pragma unroll
                    for (int j = 0; j < 4; j++) {
                        acc[i][j] += av[i].x * wv[j].x;
                        acc[i][j] += av[i].y * wv[j].y;
                        acc[i][j] += av[i].z * wv[j].z;
                        acc[i][j] += av[i].w * wv[j].w;
                    }
            }
            __syncthreads();
        }
#pragma unroll
        for (int i = 0; i < 4; i++)
            *(float4*)&lo[(size_t)(tok0 + tr * 4 + i) * E + ec * 4] =
                make_float4(acc[i][0], acc[i][1], acc[i][2], acc[i][3]);
        __syncthreads();   // logits visible block-wide (via L2/global)
    }

    // ---- gate: warp w handles tokens tok0 + w*8 .. +7 ----------------------
    float mea = 0.0f, meb = 0.0f;
    for (int r = 0; r < 8; r++) {
        int t = tok0 + w * 8 + r;

        float l1a = g_logits1[(size_t)t * E + lane];
        float l1b = g_logits1[(size_t)t * E + 32 + lane];
        if (lane == 0) l1a = -1e9f;      // expert 0 excluded

        bool sela = false, selb = false;
#pragma unroll 1
        for (int it = 0; it < 16; it++) {
            float va = sela ? -FLT_MAX : l1a;
            float vb = selb ? -FLT_MAX : l1b;
            float v; int idx;
            if (vb > va) { v = vb; idx = lane + 32; } else { v = va; idx = lane; }
#pragma unroll
            for (int off = 16; off > 0; off >>= 1) {
                float ov = __shfl_xor_sync(0xffffffffu, v, off);
                int   oi = __shfl_xor_sync(0xffffffffu, idx, off);
                if (ov > v || (ov == v && oi < idx)) { v = ov; idx = oi; }
            }
            if (idx == lane) sela = true;
            else if (idx == lane + 32) selb = true;
        }

        float l2a = g_logits2[(size_t)t * E + lane];
        float l2b = g_logits2[(size_t)t * E + 32 + lane];
        float va = sela ? l2a : -FLT_MAX;
        float vb = selb ? l2b : -FLT_MAX;
        float m; int ei;
        if (vb > va) { m = vb; ei = lane + 32; } else { m = va; ei = lane; }
#pragma unroll
        for (int off = 16; off > 0; off >>= 1) {
            float ov = __shfl_xor_sync(0xffffffffu, m, off);
            int   oi = __shfl_xor_sync(0xffffffffu, ei, off);
            if (ov > m || (ov == m && oi < ei)) { m = ov; ei = oi; }
        }

        float ea = sela ? expf(l2a - m) : 0.0f;
        float eb = selb ? expf(l2b - m) : 0.0f;
        float ssum = ea + eb;
#pragma unroll
        for (int off = 16; off > 0; off >>= 1)
            ssum += __shfl_xor_sync(0xffffffffu, ssum, off);
        float inv = 1.0f / ssum;

        if (sela) mea += ea * inv;
        if (selb) meb += eb * inv;
        if (lane == 0) { g_expert[t] = ei; g_gate[t] = inv; }
    }

    // ---- me partials (no atomics): block-reduce over 8 warps ---------------
    sA[w * 64 + lane]      = mea;
    sA[w * 64 + 32 + lane] = meb;
    __syncthreads();
    if (tid < 64) {
        float s = 0.0f;
#pragma unroll
        for (int ww = 0; ww < 8; ww++) s += sA[ww * 64 + tid];
        g_me_part[b * 64 + tid] = s;
    }
}

// ---------------- locations via match.any ballots + l_aux ------------------
__global__ __launch_bounds__(1024) void loc_kernel() {
    __shared__ int   sCnt[128][E];     // per-window per-expert counts (32 KB)
    __shared__ float sPart[16][E];     // me reduction staging (4 KB)
    __shared__ float sMe[E];

    const int tid  = threadIdx.x;
    const int lane = tid & 31;
    const int wp   = tid >> 5;         // warp id 0..31

    for (int i = tid; i < 128 * E; i += 1024) ((int*)sCnt)[i] = 0;
    __syncthreads();

    int   eReg[4];
    unsigned mReg[4];
#pragma unroll
    for (int k = 0; k < 4; k++) {
        int win = wp + k * 32;
        int e   = g_expert[win * 32 + lane];
        unsigned mask = __match_any_sync(0xffffffffu, e);
        eReg[k] = e; mReg[k] = mask;
        if ((mask & ((1u << lane) - 1)) == 0)     // leader lane of group
            sCnt[win][e] = __popc(mask);
    }

    {   // me partial reduction: thread (i = tid>>6, e = tid&63) sums 4 blocks
        int e = tid & 63, i = tid >> 6;
        float s = 0.0f;
        for (int b = i * 4; b < (i + 1) * 4; b++) s += g_me_part[b * 64 + e];
        sPart[i][e] = s;
    }
    __syncthreads();

    if (tid < 64) {                    // exclusive window-scan; ce = total
        int run = 0;
#pragma unroll 4
        for (int win = 0; win < 128; win++) {
            int c = sCnt[win][tid];
            sCnt[win][tid] = run;
            run += c;
        }
        float me = 0.0f;
#pragma unroll
        for (int i = 0; i < 16; i++) me += sPart[i][tid];
        sMe[tid] = me * (float)run;
    }
    __syncthreads();

#pragma unroll
    for (int k = 0; k < 4; k++) {
        int win  = wp + k * 32;
        int rank = sCnt[win][eReg[k]] + __popc(mReg[k] & ((1u << lane) - 1));
        g_loc[win * 32 + lane] = rank;
    }

    if (tid == 0) {
        float sum = 0.0f;
        for (int ee = 0; ee < E; ee++) sum += sMe[ee];
        g_laux = sum * (1.0f / 65536.0f);   // sum(me*ce)/(S*S)/num_2nd*E*E
    }
}

// ---------------- sparse scatter into combine/dispatch + l_aux -------------
__global__ void scatter_kernel(float* __restrict__ out) {
    int s = blockIdx.x * 256 + threadIdx.x;
    if (s == 0) out[0] = g_laux;
    if (s >= S) return;
    int loc = g_loc[s];
    if (loc >= CAP) return;            // dropped token: everything stays 0
    size_t off = ((size_t)s * E + g_expert[s]) * CAP + loc;
    out[1 + off] = g_gate[s];
    out[1 + (size_t)S * ROW + off] = 1.0f;
}

// ---------------- launch ----------------------------------------------------
extern "C" void kernel_launch(void* const* d_in, const int* in_sizes, int n_in,
                              void* d_out, int out_size) {
    const float* input1 = (const float*)d_in[0];
    const float* input2 = (const float*)d_in[1];
    const float* wg1    = (const float*)d_in[2];
    const float* wg2    = (const float*)d_in[3];
    float* out = (float*)d_out;

    const long long n4 = (long long)out_size / 4;
    const bool forked = (g_s1 && g_evFork && g_evJoin);

    if (forked) {
        // Fork: 64-block fused chain + loc on side stream, under the fill.
        cudaEventRecord(g_evFork, 0);
        cudaStreamWaitEvent(g_s1, g_evFork, 0);

        chain_kernel<<<NCHAIN, 256, 0, g_s1>>>(input1, input2, wg1, wg2);
        loc_kernel<<<1, 1024, 0, g_s1>>>();
        cudaEventRecord(g_evJoin, g_s1);

        // Dominant cost: zero 1.07 GB at ~7 TB/s (measured).
        zero_fill_kernel<<<ZF_BLOCKS, 256>>>((float4*)out, out, n4,
                                             (long long)out_size);

        // Join, then sparse scatter into the zeroed buffer.
        cudaStreamWaitEvent(0, g_evJoin, 0);
        scatter_kernel<<<(S + 255) / 256, 256>>>(out);
    } else {
        // Fallback: fully serial on the captured stream.
        zero_fill_kernel<<<ZF_BLOCKS, 256>>>((float4*)out, out, n4,
                                             (long long)out_size);
        chain_kernel<<<NCHAIN, 256>>>(input1, input2, wg1, wg2);
        loc_kernel<<<1, 1024>>>();
        scatter_kernel<<<(S + 255) / 256, 256>>>(out);
    }
}

// round 14
// speedup vs baseline: 1.0789x; 1.0789x over previous
#include <cuda_runtime.h>
#include <cuda_bf16.h>
#include <cfloat>

// Problem constants (S=4096 tokens, D=1024 dim, E=64 experts)
constexpr int S   = 4096;
constexpr int D   = 1024;
constexpr int E   = 64;
constexpr int CAP = 512;          // 2 * ceil(S / (E/4))
constexpr int NCHAIN = 128;       // fused gemm+gate blocks (32 tokens each)
constexpr int ROW  = E * CAP;     // 32768 floats per token per tensor
// out layout (float32): [0] = l_aux, [1 .. 1+S*E*CAP) = combine, then dispatch

// ---------------- scratch (device globals; no allocation allowed) ----------
__device__ int   g_expert[S];
__device__ float g_gate[S];
__device__ int   g_loc[S];
__device__ float g_me_part[NCHAIN * E];
__device__ float g_laux;

// ---------------- priority side stream + events ----------------------------
static cudaStream_t g_s1 = nullptr;
static cudaEvent_t  g_evFork = nullptr, g_evJoin = nullptr;
namespace {
struct StreamInit {
    StreamInit() {
        int lo = 0, hi = 0;
        cudaDeviceGetStreamPriorityRange(&lo, &hi);   // hi = highest priority
        if (cudaStreamCreateWithPriority(&g_s1, cudaStreamNonBlocking, hi)
                != cudaSuccess) {
            if (cudaStreamCreateWithFlags(&g_s1, cudaStreamNonBlocking)
                    != cudaSuccess)
                g_s1 = nullptr;
        }
        if (cudaEventCreateWithFlags(&g_evFork, cudaEventDisableTiming) != cudaSuccess)
            g_evFork = nullptr;
        if (cudaEventCreateWithFlags(&g_evJoin, cudaEventDisableTiming) != cudaSuccess)
            g_evJoin = nullptr;
    }
};
static StreamInit g_streamInit;
}

// ---------------- bulk zero fill (R12-measured 7.0 TB/s — FROZEN) ----------
constexpr int ZF_BLOCKS = 2 * S;                  // 8192
constexpr int ZF_CHUNK4 = 8192;                   // float4s per block (128 KB)

__global__ __launch_bounds__(256) void zero_fill_kernel(
    float4* __restrict__ p4,
    float* __restrict__ out, long long n4, long long out_elems)
{
    const float4 z = make_float4(0.f, 0.f, 0.f, 0.f);
    float4* base = p4 + (long long)blockIdx.x * ZF_CHUNK4;
#pragma unroll 4
    for (int j = threadIdx.x; j < ZF_CHUNK4; j += 256)
        base[j] = z;
    if (blockIdx.x == 0) {            // scalar tail (out_size % 4 elements)
        for (long long j = n4 * 4 + threadIdx.x; j < out_elems; j += 256)
            out[j] = 0.0f;
    }
}

// ---------------- fused chain: both GEMMs + gate, 128 blocks ---------------
// Block b: tokens b*32..b*32+31. Both 32x64 logit tiles computed and kept in
// SMEM (no global logits round-trip). K-chunks of 32. Then warps gate 4
// tokens each straight from smem.
__global__ __launch_bounds__(256) void chain_kernel(
    const float* __restrict__ A1, const float* __restrict__ A2,
    const float* __restrict__ W1, const float* __restrict__ W2)
{
    __shared__ float sA[32 * 32];         // 4 KB
    __shared__ float sW[64 * 32];         // 8 KB
    __shared__ float sLog[2][32][64];     // 16 KB

    const int b    = blockIdx.x;
    const int tid  = threadIdx.x;
    const int lane = tid & 31;
    const int w    = tid >> 5;

    const int tok0 = b * 32;
    const int tr = tid & 15;          // token pair  (tokens tr*2, tr*2+1)
    const int ec = tid >> 4;          // expert quad (experts ec*4..+3)
    const int lrow = tid >> 3;        // loader row 0..31
    const int lc   = tid & 7;         // loader float4 col 0..7
    const int swzA = (tr >> 1) & 7;   // (tr*2)>>2 == (tr*2+1)>>2 == tr>>1
    const int swzW = ec & 7;          // (ec*4+j)>>2 == ec for j<4

    for (int p = 0; p < 2; p++) {
        const float* A = p ? A2 : A1;
        const float* W = p ? W2 : W1;

        float acc[2][4];
#pragma unroll
        for (int i = 0; i < 2; i++)
#pragma unroll
            for (int j = 0; j < 4; j++) acc[i][j] = 0.0f;

        float4 pa, pw0, pw1;
        pa  = *(const float4*)&A[(size_t)(tok0 + lrow) * D + lc * 4];
        pw0 = *(const float4*)&W[(size_t)lrow * D + lc * 4];
        pw1 = *(const float4*)&W[(size_t)(lrow + 32) * D + lc * 4];

        for (int kt = 0; kt < D; kt += 32) {
            {   // swizzled stores: phys col = lc ^ ((row>>2)&7)
                int sc0 = (lc ^ ((lrow >> 2) & 7)) * 4;
                int sc1 = (lc ^ (((lrow + 32) >> 2) & 7)) * 4;
                *(float4*)&sA[lrow * 32 + sc0]        = pa;
                *(float4*)&sW[lrow * 32 + sc0]        = pw0;
                *(float4*)&sW[(lrow + 32) * 32 + sc1] = pw1;
            }
            __syncthreads();

            if (kt + 32 < D) {
                pa  = *(const float4*)&A[(size_t)(tok0 + lrow) * D + kt + 32 + lc * 4];
                pw0 = *(const float4*)&W[(size_t)lrow * D + kt + 32 + lc * 4];
                pw1 = *(const float4*)&W[(size_t)(lrow + 32) * D + kt + 32 + lc * 4];
            }

#pragma unroll
            for (int kk = 0; kk < 8; kk++) {
                float4 av[2], wv[4];
#pragma unroll
                for (int i = 0; i < 2; i++)
                    av[i] = *(const float4*)&sA[(tr * 2 + i) * 32 + ((kk ^ swzA) * 4)];
#pragma unroll
                for (int j = 0; j < 4; j++)
                    wv[j] = *(const float4*)&sW[(ec * 4 + j) * 32 + ((kk ^ swzW) * 4)];
#pragma unroll
                for (int i = 0; i < 2; i++)
#pragma unroll
                    for (int j = 0; j < 4; j++) {
                        acc[i][j] += av[i].x * wv[j].x;
                        acc[i][j] += av[i].y * wv[j].y;
                        acc[i][j] += av[i].z * wv[j].z;
                        acc[i][j] += av[i].w * wv[j].w;
                    }
            }
            __syncthreads();
        }

        // logits tile -> smem (no global round-trip)
#pragma unroll
        for (int i = 0; i < 2; i++)
#pragma unroll
            for (int j = 0; j < 4; j++)
                sLog[p][tr * 2 + i][ec * 4 + j] = acc[i][j];
        __syncthreads();
    }

    // ---- gate: warp w handles local tokens w*4 .. w*4+3 --------------------
    float mea = 0.0f, meb = 0.0f;
    for (int r = 0; r < 4; r++) {
        int tok = w * 4 + r;
        int t   = tok0 + tok;

        float l1a = sLog[0][tok][lane];
        float l1b = sLog[0][tok][32 + lane];
        if (lane == 0) l1a = -1e9f;      // expert 0 excluded

        bool sela = false, selb = false;
#pragma unroll 1
        for (int it = 0; it < 16; it++) {
            float va = sela ? -FLT_MAX : l1a;
            float vb = selb ? -FLT_MAX : l1b;
            float v; int idx;
            if (vb > va) { v = vb; idx = lane + 32; } else { v = va; idx = lane; }
#pragma unroll
            for (int off = 16; off > 0; off >>= 1) {
                float ov = __shfl_xor_sync(0xffffffffu, v, off);
                int   oi = __shfl_xor_sync(0xffffffffu, idx, off);
                if (ov > v || (ov == v && oi < idx)) { v = ov; idx = oi; }
            }
            if (idx == lane) sela = true;
            else if (idx == lane + 32) selb = true;
        }

        float l2a = sLog[1][tok][lane];
        float l2b = sLog[1][tok][32 + lane];
        float va = sela ? l2a : -FLT_MAX;
        float vb = selb ? l2b : -FLT_MAX;
        float m; int ei;
        if (vb > va) { m = vb; ei = lane + 32; } else { m = va; ei = lane; }
#pragma unroll
        for (int off = 16; off > 0; off >>= 1) {
            float ov = __shfl_xor_sync(0xffffffffu, m, off);
            int   oi = __shfl_xor_sync(0xffffffffu, ei, off);
            if (ov > m || (ov == m && oi < ei)) { m = ov; ei = oi; }
        }

        float ea = sela ? expf(l2a - m) : 0.0f;
        float eb = selb ? expf(l2b - m) : 0.0f;
        float ssum = ea + eb;
#pragma unroll
        for (int off = 16; off > 0; off >>= 1)
            ssum += __shfl_xor_sync(0xffffffffu, ssum, off);
        float inv = 1.0f / ssum;

        if (sela) mea += ea * inv;
        if (selb) meb += eb * inv;
        if (lane == 0) { g_expert[t] = ei; g_gate[t] = inv; }
    }

    // ---- me partials: block-reduce over 8 warps (reuse sA) -----------------
    __syncthreads();
    sA[w * 64 + lane]      = mea;
    sA[w * 64 + 32 + lane] = meb;
    __syncthreads();
    if (tid < 64) {
        float s = 0.0f;
#pragma unroll
        for (int ww = 0; ww < 8; ww++) s += sA[ww * 64 + tid];
        g_me_part[b * 64 + tid] = s;
    }
}

// ---------------- locations via match.any ballots + l_aux ------------------
__global__ __launch_bounds__(1024) void loc_kernel() {
    __shared__ int   sCnt[128][E];     // per-window per-expert counts (32 KB)
    __shared__ float sPart[16][E];     // me reduction staging (4 KB)
    __shared__ float sMe[E];

    const int tid  = threadIdx.x;
    const int lane = tid & 31;
    const int wp   = tid >> 5;         // warp id 0..31

    for (int i = tid; i < 128 * E; i += 1024) ((int*)sCnt)[i] = 0;
    __syncthreads();

    int   eReg[4];
    unsigned mReg[4];
#pragma unroll
    for (int k = 0; k < 4; k++) {
        int win = wp + k * 32;
        int e   = g_expert[win * 32 + lane];
        unsigned mask = __match_any_sync(0xffffffffu, e);
        eReg[k] = e; mReg[k] = mask;
        if ((mask & ((1u << lane) - 1)) == 0)     // leader lane of group
            sCnt[win][e] = __popc(mask);
    }

    {   // me partial reduction: thread (i = tid>>6, e = tid&63) sums 8 blocks
        int e = tid & 63, i = tid >> 6;
        float s = 0.0f;
        for (int b = i * 8; b < (i + 1) * 8; b++) s += g_me_part[b * 64 + e];
        sPart[i][e] = s;
    }
    __syncthreads();

    if (tid < 64) {                    // exclusive window-scan; ce = total
        int run = 0;
#pragma unroll 4
        for (int win = 0; win < 128; win++) {
            int c = sCnt[win][tid];
            sCnt[win][tid] = run;
            run += c;
        }
        float me = 0.0f;
#pragma unroll
        for (int i = 0; i < 16; i++) me += sPart[i][tid];
        sMe[tid] = me * (float)run;
    }
    __syncthreads();

#pragma unroll
    for (int k = 0; k < 4; k++) {
        int win  = wp + k * 32;
        int rank = sCnt[win][eReg[k]] + __popc(mReg[k] & ((1u << lane) - 1));
        g_loc[win * 32 + lane] = rank;
    }

    if (tid == 0) {
        float sum = 0.0f;
        for (int ee = 0; ee < E; ee++) sum += sMe[ee];
        g_laux = sum * (1.0f / 65536.0f);   // sum(me*ce)/(S*S)/num_2nd*E*E
    }
}

// ---------------- sparse scatter into combine/dispatch + l_aux -------------
__global__ void scatter_kernel(float* __restrict__ out) {
    int s = blockIdx.x * 256 + threadIdx.x;
    if (s == 0) out[0] = g_laux;
    if (s >= S) return;
    int loc = g_loc[s];
    if (loc >= CAP) return;            // dropped token: everything stays 0
    size_t off = ((size_t)s * E + g_expert[s]) * CAP + loc;
    out[1 + off] = g_gate[s];
    out[1 + (size_t)S * ROW + off] = 1.0f;
}

// ---------------- launch ----------------------------------------------------
extern "C" void kernel_launch(void* const* d_in, const int* in_sizes, int n_in,
                              void* d_out, int out_size) {
    const float* input1 = (const float*)d_in[0];
    const float* input2 = (const float*)d_in[1];
    const float* wg1    = (const float*)d_in[2];
    const float* wg2    = (const float*)d_in[3];
    float* out = (float*)d_out;

    const long long n4 = (long long)out_size / 4;
    const bool forked = (g_s1 && g_evFork && g_evJoin);

    if (forked) {
        // Fork: low-traffic chain + loc on the PRIORITY side stream.
        cudaEventRecord(g_evFork, 0);
        cudaStreamWaitEvent(g_s1, g_evFork, 0);

        chain_kernel<<<NCHAIN, 256, 0, g_s1>>>(input1, input2, wg1, wg2);
        loc_kernel<<<1, 1024, 0, g_s1>>>();
        cudaEventRecord(g_evJoin, g_s1);

        // Dominant cost: zero 1.07 GB at 7.0 TB/s (measured, frozen).
        zero_fill_kernel<<<ZF_BLOCKS, 256>>>((float4*)out, out, n4,
                                             (long long)out_size);

        // Join, then sparse scatter into the zeroed buffer.
        cudaStreamWaitEvent(0, g_evJoin, 0);
        scatter_kernel<<<(S + 255) / 256, 256>>>(out);
    } else {
        // Fallback: fully serial on the captured stream.
        zero_fill_kernel<<<ZF_BLOCKS, 256>>>((float4*)out, out, n4,
                                             (long long)out_size);
        chain_kernel<<<NCHAIN, 256>>>(input1, input2, wg1, wg2);
        loc_kernel<<<1, 1024>>>();
        scatter_kernel<<<(S + 255) / 256, 256>>>(out);
    }
}

// round 16
// speedup vs baseline: 1.3748x; 1.2744x over previous
#include <cuda_runtime.h>
#include <cuda_bf16.h>
#include <cfloat>

// Problem constants (S=4096 tokens, D=1024 dim, E=64 experts)
constexpr int S   = 4096;
constexpr int D   = 1024;
constexpr int E   = 64;
constexpr int CAP = 512;          // 2 * ceil(S / (E/4))
constexpr int KSLICES = 4;        // split-K factor (K-slice = 256)
constexpr int KS      = D / KSLICES;
constexpr int NGATE   = S / 8;    // gate blocks (8 tokens each)
constexpr int ROW     = E * CAP;  // 32768 floats per token per tensor
// out layout (float32): [0] = l_aux, [1 .. 1+S*E*CAP) = combine, then dispatch

// Fill partition (in float4 units). Total n4 = 2*S*ROW/4 = 67108864.
constexpr long long GEMM_F4_PER_BLK = 16384;   // 256 KB x 1024 blocks = 256 MB
constexpr long long GATE_F4_PER_BLK = 8192;    // 128 KB x 512 blocks  =  64 MB
constexpr long long GEMM_F4_TOTAL   = GEMM_F4_PER_BLK * 1024;   // 16777216
constexpr long long GATE_F4_TOTAL   = GATE_F4_PER_BLK * NGATE;  //  4194304
constexpr long long FILL_BASE       = GEMM_F4_TOTAL + GATE_F4_TOTAL;
constexpr int       ZF_BLOCKS       = 8192;
constexpr long long ZF_CHUNK4       = 5632;    // 8192*5632 = 46137344 (rest)

// ---------------- scratch (device globals; no allocation allowed) ----------
__device__ float g_part[2 * KSLICES * S * E];    // split-K partial logits (8MB)
__device__ int   g_expert[S];
__device__ float g_gate[S];
__device__ int   g_loc[S];
__device__ float g_me_part[NGATE * E];
__device__ float g_laux;

// ---------------- split-K GEMM + embedded fill -----------------------------
// grid (64 tok-tiles, 2 gemms, 4 K-slices) = 1024 blocks. Tile 64x64,
// K-chunks of 64 (R12-proven math). Each block additionally zeroes a
// contiguous 256KB slice of d_out, 16 float4-stores per thread per K-iter,
// issued after the prefetch loads so they drain under the compute.
__global__ __launch_bounds__(256) void gemm_kernel(
    const float* __restrict__ A1, const float* __restrict__ A2,
    const float* __restrict__ W1, const float* __restrict__ W2,
    float4* __restrict__ out4)
{
    const float* A = blockIdx.y ? A2 : A1;
    const float* W = blockIdx.y ? W2 : W1;
    float* out = g_part + ((size_t)(blockIdx.y * KSLICES + blockIdx.z)) * S * E;
    const int tok0 = blockIdx.x * 64;
    const int kt0  = blockIdx.z * KS;

    const int blin = blockIdx.x + 64 * (blockIdx.y + 2 * blockIdx.z); // 0..1023
    float4* fill = out4 + (long long)blin * GEMM_F4_PER_BLK;
    const float4 z = make_float4(0.f, 0.f, 0.f, 0.f);

    __shared__ float As[64 * 64];
    __shared__ float Ws[64 * 64];

    const int tid = threadIdx.x;
    const int lr  = tid >> 4;   // loader row base (0..15)
    const int lc  = tid & 15;   // loader float4 column (0..15)
    const int tr  = tid & 15;   // compute: token quad
    const int ec  = tid >> 4;   // compute: expert quad

    float acc[4][4];
#pragma unroll
    for (int i = 0; i < 4; i++)
#pragma unroll
        for (int j = 0; j < 4; j++) acc[i][j] = 0.0f;

    float4 pa[4], pw[4];
#pragma unroll
    for (int p = 0; p < 4; p++) {
        int row = lr + p * 16;
        pa[p] = *(const float4*)&A[(size_t)(tok0 + row) * D + kt0 + lc * 4];
        pw[p] = *(const float4*)&W[(size_t)row * D + kt0 + lc * 4];
    }

    int it = 0;
    for (int kt = kt0; kt < kt0 + KS; kt += 64, it++) {
#pragma unroll
        for (int p = 0; p < 4; p++) {
            int row = lr + p * 16;
            int sc  = (lc ^ ((row >> 2) & 7)) * 4;
            *(float4*)&As[row * 64 + sc] = pa[p];
            *(float4*)&Ws[row * 64 + sc] = pw[p];
        }
        __syncthreads();

        if (kt + 64 < kt0 + KS) {
#pragma unroll
            for (int p = 0; p < 4; p++) {
                int row = lr + p * 16;
                pa[p] = *(const float4*)&A[(size_t)(tok0 + row) * D + kt + 64 + lc * 4];
                pw[p] = *(const float4*)&W[(size_t)row * D + kt + 64 + lc * 4];
            }
        }

        // embedded fill: 16 posted stores per thread, drain under compute
        {
            float4* fb = fill + (long long)it * 4096;
#pragma unroll
            for (int k = 0; k < 16; k++) fb[k * 256 + tid] = z;
        }

#pragma unroll
        for (int kk = 0; kk < 16; kk++) {
            float4 av[4], wv[4];
#pragma unroll
            for (int i = 0; i < 4; i++) {
                int tok = tr * 4 + i;
                av[i] = *(const float4*)&As[tok * 64 + ((kk ^ (tr & 7)) * 4)];
                int e = ec * 4 + i;
                wv[i] = *(const float4*)&Ws[e * 64 + ((kk ^ (ec & 7)) * 4)];
            }
#pragma unroll
            for (int i = 0; i < 4; i++)
#pragma unroll
                for (int j = 0; j < 4; j++) {
                    acc[i][j] += av[i].x * wv[j].x;
                    acc[i][j] += av[i].y * wv[j].y;
                    acc[i][j] += av[i].z * wv[j].z;
                    acc[i][j] += av[i].w * wv[j].w;
                }
        }
        __syncthreads();
    }

#pragma unroll
    for (int i = 0; i < 4; i++)
        *(float4*)&out[(size_t)(tok0 + tr * 4 + i) * E + ec * 4] =
            make_float4(acc[i][0], acc[i][1], acc[i][2], acc[i][3]);
}

// ---------------- gating (R12-proven) + embedded fill ----------------------
__global__ __launch_bounds__(256) void gate_kernel(float4* __restrict__ out4) {
    __shared__ float sMe[8 * 64];
    const int b    = blockIdx.x;
    const int tid  = threadIdx.x;
    const int lane = tid & 31;
    const int w    = tid >> 5;
    const int t    = b * 8 + w;

    float l1a = 0.f, l1b = 0.f, l2a = 0.f, l2b = 0.f;
#pragma unroll
    for (int kz = 0; kz < KSLICES; kz++) {
        const float* p1 = g_part + (size_t)kz * S * E + (size_t)t * E;
        const float* p2 = g_part + (size_t)(KSLICES + kz) * S * E + (size_t)t * E;
        l1a += p1[lane];  l1b += p1[32 + lane];
        l2a += p2[lane];  l2b += p2[32 + lane];
    }
    if (lane == 0) l1a = -1e9f;      // expert 0 excluded from group gating

    // embedded fill: 32 posted stores per thread, drain under the gating math
    {
        float4* fb = out4 + GEMM_F4_TOTAL + (long long)b * GATE_F4_PER_BLK;
        const float4 z = make_float4(0.f, 0.f, 0.f, 0.f);
#pragma unroll
        for (int k = 0; k < 32; k++) fb[k * 256 + tid] = z;
    }

    // ---- stage 1: top-16 of group logits (softmax monotone -> skip it)
    bool sela = false, selb = false;
#pragma unroll 1
    for (int it = 0; it < 16; it++) {
        float va = sela ? -FLT_MAX : l1a;
        float vb = selb ? -FLT_MAX : l1b;
        float v; int idx;
        if (vb > va) { v = vb; idx = lane + 32; } else { v = va; idx = lane; }
#pragma unroll
        for (int off = 16; off > 0; off >>= 1) {
            float ov = __shfl_xor_sync(0xffffffffu, v, off);
            int   oi = __shfl_xor_sync(0xffffffffu, idx, off);
            if (ov > v || (ov == v && oi < idx)) { v = ov; idx = oi; }
        }
        if (idx == lane) sela = true;
        else if (idx == lane + 32) selb = true;
    }

    // ---- stage 2: masked softmax over the 16 selected experts
    float va = sela ? l2a : -FLT_MAX;
    float vb = selb ? l2b : -FLT_MAX;
    float m; int ei;
    if (vb > va) { m = vb; ei = lane + 32; } else { m = va; ei = lane; }
#pragma unroll
    for (int off = 16; off > 0; off >>= 1) {
        float ov = __shfl_xor_sync(0xffffffffu, m, off);
        int   oi = __shfl_xor_sync(0xffffffffu, ei, off);
        if (ov > m || (ov == m && oi < ei)) { m = ov; ei = oi; }
    }

    float ea = sela ? expf(l2a - m) : 0.0f;
    float eb = selb ? expf(l2b - m) : 0.0f;
    float ssum = ea + eb;
#pragma unroll
    for (int off = 16; off > 0; off >>= 1)
        ssum += __shfl_xor_sync(0xffffffffu, ssum, off);
    float inv = 1.0f / ssum;

    if (lane == 0) { g_expert[t] = ei; g_gate[t] = inv; }

    sMe[w * 64 + lane]      = sela ? ea * inv : 0.0f;
    sMe[w * 64 + 32 + lane] = selb ? eb * inv : 0.0f;
    __syncthreads();
    if (tid < 64) {
        float s = 0.0f;
#pragma unroll
        for (int ww = 0; ww < 8; ww++) s += sMe[ww * 64 + tid];
        g_me_part[b * 64 + tid] = s;
    }
}

// ---------------- locations via match.any ballots + l_aux (R12-proven) -----
__global__ __launch_bounds__(1024) void loc_kernel() {
    __shared__ int   sCnt[128][E];     // per-window per-expert counts (32 KB)
    __shared__ float sPart[16][E];     // me reduction staging (4 KB)
    __shared__ float sMe[E];

    const int tid  = threadIdx.x;
    const int lane = tid & 31;
    const int wp   = tid >> 5;         // warp id 0..31

    for (int i = tid; i < 128 * E; i += 1024) ((int*)sCnt)[i] = 0;
    __syncthreads();

    int   eReg[4];
    unsigned mReg[4];
#pragma unroll
    for (int k = 0; k < 4; k++) {
        int win = wp + k * 32;
        int e   = g_expert[win * 32 + lane];
        unsigned mask = __match_any_sync(0xffffffffu, e);
        eReg[k] = e; mReg[k] = mask;
        if ((mask & ((1u << lane) - 1)) == 0)     // leader lane of group
            sCnt[win][e] = __popc(mask);
    }

    {   // me partial reduction over NGATE=512 gate blocks
        int e = tid & 63, i = tid >> 6;
        float s = 0.0f;
        for (int b = i * 32; b < (i + 1) * 32; b++) s += g_me_part[b * 64 + e];
        sPart[i][e] = s;
    }
    __syncthreads();

    if (tid < 64) {                    // exclusive window-scan; ce = total
        int run = 0;
#pragma unroll 4
        for (int win = 0; win < 128; win++) {
            int c = sCnt[win][tid];
            sCnt[win][tid] = run;
            run += c;
        }
        float me = 0.0f;
#pragma unroll
        for (int i = 0; i < 16; i++) me += sPart[i][tid];
        sMe[tid] = me * (float)run;
    }
    __syncthreads();

#pragma unroll
    for (int k = 0; k < 4; k++) {
        int win  = wp + k * 32;
        int rank = sCnt[win][eReg[k]] + __popc(mReg[k] & ((1u << lane) - 1));
        g_loc[win * 32 + lane] = rank;
    }

    if (tid == 0) {
        float sum = 0.0f;
        for (int ee = 0; ee < E; ee++) sum += sMe[ee];
        g_laux = sum * (1.0f / 65536.0f);   // sum(me*ce)/(S*S)/num_2nd*E*E
    }
}

// ---------------- remainder zero fill (frozen 7.0 TB/s structure) ----------
__global__ __launch_bounds__(256) void zero_fill_kernel(
    float4* __restrict__ p4,
    float* __restrict__ out, long long n4, long long out_elems)
{
    const float4 z = make_float4(0.f, 0.f, 0.f, 0.f);
    float4* base = p4 + FILL_BASE + (long long)blockIdx.x * ZF_CHUNK4;
#pragma unroll 4
    for (int j = threadIdx.x; j < (int)ZF_CHUNK4; j += 256)
        base[j] = z;
    if (blockIdx.x == 0) {            // scalar tail (out_size % 4 elements)
        for (long long j = n4 * 4 + threadIdx.x; j < out_elems; j += 256)
            out[j] = 0.0f;
    }
}

// ---------------- sparse scatter into combine/dispatch + l_aux -------------
__global__ void scatter_kernel(float* __restrict__ out) {
    int s = blockIdx.x * 256 + threadIdx.x;
    if (s == 0) out[0] = g_laux;
    if (s >= S) return;
    int loc = g_loc[s];
    if (loc >= CAP) return;            // dropped token: everything stays 0
    size_t off = ((size_t)s * E + g_expert[s]) * CAP + loc;
    out[1 + off] = g_gate[s];
    out[1 + (size_t)S * ROW + off] = 1.0f;
}

// ---------------- launch ----------------------------------------------------
extern "C" void kernel_launch(void* const* d_in, const int* in_sizes, int n_in,
                              void* d_out, int out_size) {
    const float* input1 = (const float*)d_in[0];
    const float* input2 = (const float*)d_in[1];
    const float* wg1    = (const float*)d_in[2];
    const float* wg2    = (const float*)d_in[3];
    float* out = (float*)d_out;
    float4* out4 = (float4*)(out + 1);   // fill region starts after l_aux;
    // NOTE: out+1 is 4-byte offset -> use byte view: treat fill as covering
    // out[1 .. 1+n4*4). out+1 is not 16B-aligned, so shift: fill in float4s
    // over out[4..], and handle out[1..3] as head in scatter-side kernel.
    // Simpler: fill covers float4s of the raw buffer out[0..n4*4) and the
    // scalar tail; l_aux is rewritten by scatter (runs last). blin 0's first
    // float4 covers out[0..3] including l_aux slot - scatter overwrites [0].
    out4 = (float4*)out;

    const long long n4 = (long long)out_size / 4;   // 67108864 (tail 1 elem)

    gemm_kernel<<<dim3(S / 64, 2, KSLICES), 256>>>(input1, input2, wg1, wg2, out4);
    gate_kernel<<<NGATE, 256>>>(out4);
    loc_kernel<<<1, 1024>>>();
    zero_fill_kernel<<<ZF_BLOCKS, 256>>>(out4, out, n4, (long long)out_size);
    scatter_kernel<<<(S + 255) / 256, 256>>>(out);
}